// round 9
// baseline (speedup 1.0000x reference)
#include <cuda_runtime.h>
#include <cstdint>

// ---------------------------------------------------------------------------
// BatchTopK, ONE launch (3072 one-shot blocks):
//   - every block issues its streaming loads + zero-stores first
//   - blocks 0..95 (wave-1) also sample -> last sampler publishes guess g_gf
//   - all blocks spin on ready (overlapped with their in-flight loads),
//     filter, stage candidates, flush, take a finish ticket
//   - the LAST 148 ticket holders (co-resident by construction) become the
//     select grid: 4 race-free grid barriers, 3-level radix select,
//     winner scatter, EMA, tie fixup. All state resets happen strictly after
//     the barrier that ends the state's last read (R8 deadlock fix).
// ---------------------------------------------------------------------------

#define K_TOTAL       98304u       // 32 * 512 * 6
#define EMA_E         0.003f
#define CANDCAP       2097152u
#define SIDECAP       524288u
#define EQCAP         4096u
#define SAMPLE_TARGET 544u         // ~139k expected candidates, ~7 sigma margin
#define NT            256
#define NBS           96           // sampler blocks (768 warps * 128 floats)
#define CHUNK_F4      2048         // 256 threads * 8 float4
#define NCHUNKS       3072         // 25165824 / 4 / 2048
#define NB_SEL        148          // last-finisher select grid (1 per SM max)
#define NTHR_SEL      (NB_SEL * NT)
#define SCAP          1024u

static __device__ unsigned g_hist_s[4096];
static __device__ unsigned g_histA[4096];
static __device__ unsigned g_histB[4096];
static __device__ unsigned g_hist8[256];
static __device__ unsigned g_cand_key[CANDCAP];
static __device__ unsigned g_cand_idx[CANDCAP];
static __device__ unsigned g_side_key[SIDECAP];
static __device__ unsigned g_side_idx[SIDECAP];
static __device__ unsigned g_eq_idx[EQCAP];
static __device__ unsigned g_cand_cnt;
static __device__ unsigned g_side_cnt;
static __device__ unsigned g_eq_cnt;
static __device__ unsigned g_stick;      // sampler ticket
static __device__ unsigned g_ready;      // guess published flag
static __device__ float    g_gf;         // guess threshold (float domain)
static __device__ unsigned g_done;       // finished-block ticket counter
static __device__ unsigned g_bar;        // accumulating barrier counter
static __device__ unsigned g_base;       // barrier base (advances every run)

__device__ __forceinline__ unsigned fkey(float f) {
    unsigned u = __float_as_uint(f);
    return (u & 0x80000000u) ? ~u : (u | 0x80000000u);
}
__device__ __forceinline__ float kval(unsigned k) {
    unsigned u = (k & 0x80000000u) ? (k & 0x7FFFFFFFu) : ~k;
    return __uint_as_float(u);
}

__device__ __forceinline__ void grid_bar(unsigned target) {
    __syncthreads();
    if (threadIdx.x == 0) {
        __threadfence();
        atomicAdd(&g_bar, 1u);
        while (atomicAdd(&g_bar, 0u) < target) __nanosleep(32);
    }
    __syncthreads();
    __threadfence();
}

// Warp-aggregated shared-memory histogram add.
__device__ __forceinline__ void wagg_add(unsigned* sh, unsigned bin, bool valid) {
    unsigned lane = threadIdx.x & 31u;
    unsigned b = valid ? bin : (0x10000u + lane);
    unsigned m = __match_any_sync(0xFFFFFFFFu, b);
    if (valid && (unsigned)(__ffs(m) - 1) == lane)
        atomicAdd(&sh[bin], (unsigned)__popc(m));
}

// Warp-aggregated global append: returns slot for this lane (valid lanes only).
__device__ __forceinline__ unsigned wagg_append(unsigned* cnt, bool valid) {
    unsigned mask = __ballot_sync(0xFFFFFFFFu, valid);
    unsigned lane = threadIdx.x & 31u;
    unsigned leader = __ffs(mask) - 1u;
    unsigned base = 0;
    if (lane == leader) base = atomicAdd(cnt, (unsigned)__popc(mask));
    base = __shfl_sync(0xFFFFFFFFu, base, leader);
    return base + (unsigned)__popc(mask & ((1u << lane) - 1u));
}

// Block-wide: suffix-scan 256*PER-bin histogram; max bin with suffix >= k.
template <int PER>
__device__ void suffix_pick(const unsigned* hist, unsigned k,
                            unsigned* s_scan, unsigned* s_bin, unsigned* s_rem) {
    int t = threadIdx.x;
    unsigned p = 0;
    #pragma unroll
    for (int i = 0; i < PER; i++) p += hist[t * PER + i];
    s_scan[t] = p;
    __syncthreads();
    for (int d = 1; d < 256; d <<= 1) {
        unsigned v = (t + d < 256) ? s_scan[t + d] : 0u;
        __syncthreads();
        s_scan[t] += v;
        __syncthreads();
    }
    if (s_scan[0] < k) {
        if (t == 0) { *s_bin = 0; *s_rem = 1; }
    } else {
        bool mine = (s_scan[t] >= k) && (t == 255 || s_scan[t + 1] < k);
        if (mine) {
            unsigned running = (t == 255) ? 0u : s_scan[t + 1];
            unsigned bsel = (unsigned)(t * PER);
            unsigned rem = 1;
            for (int i = PER - 1; i >= 0; i--) {
                unsigned h = hist[t * PER + i];
                if (running + h >= k) { bsel = (unsigned)(t * PER + i); rem = k - running; break; }
                running += h;
            }
            *s_bin = bsel; *s_rem = rem;
        }
    }
    __syncthreads();
}

// ---------------------------------------------------------------------------
__global__ void __launch_bounds__(NT) k_all(const float4* __restrict__ x4,
                                            float4* __restrict__ o4, int n4,
                                            const float* __restrict__ thr,
                                            float* __restrict__ out, int ntot) {
    __shared__ union {
        unsigned hist[4096];
        struct { unsigned key[SCAP]; unsigned idx[SCAP]; } st;
    } u;
    __shared__ unsigned s_scan[256];
    __shared__ unsigned s_bin, s_rem, s_cnt, s_gbase, s_tick;
    __shared__ bool s_last;
    const int t = threadIdx.x;
    const int bid = blockIdx.x;

    // ---- Issue streaming loads + zero stores FIRST (independent of guess) ----
    int base4 = bid * CHUNK_F4 + t;
    float4 v[8];
    const float4 z4 = make_float4(0.f, 0.f, 0.f, 0.f);
    if ((bid + 1) * CHUNK_F4 <= n4) {
        #pragma unroll
        for (int i = 0; i < 8; i++) v[i] = __ldcs(&x4[base4 + i * NT]);
        #pragma unroll
        for (int i = 0; i < 8; i++) __stcs(&o4[base4 + i * NT], z4);
    } else {
        #pragma unroll
        for (int i = 0; i < 8; i++) {
            int idx = base4 + i * NT;
            if (idx < n4) { v[i] = __ldcs(&x4[idx]); __stcs(&o4[idx], z4); }
            else v[i] = make_float4(-1e30f, -1e30f, -1e30f, -1e30f);
        }
    }

    // ---- Sampler blocks (wave-1 guaranteed): build guess ----
    if (bid < NBS) {
        for (int i = t; i < 4096; i += NT) u.hist[i] = 0;
        __syncthreads();
        const int warp = bid * 8 + (t >> 5);        // 0..767
        const int lane = t & 31;
        long long pos = (long long)warp * (n4 / (NBS * 8)) + lane;
        float4 sv = x4[pos];
        wagg_add(u.hist, fkey(sv.x) >> 20, true);
        wagg_add(u.hist, fkey(sv.y) >> 20, true);
        wagg_add(u.hist, fkey(sv.z) >> 20, true);
        wagg_add(u.hist, fkey(sv.w) >> 20, true);
        __syncthreads();
        for (int i = t; i < 4096; i += NT) {
            unsigned c = u.hist[i];
            if (c) atomicAdd(&g_hist_s[i], c);
        }
        __threadfence();
        __syncthreads();
        if (t == 0) s_last = (atomicAdd(&g_stick, 1u) == NBS - 1);
        __syncthreads();
        if (s_last) {
            __threadfence();
            suffix_pick<16>(g_hist_s, SAMPLE_TARGET, s_scan, &s_bin, &s_rem);
            for (int i = t; i < 4096; i += NT) g_hist_s[i] = 0;  // next-run reset
            if (t == 0) {
                g_gf = kval(s_bin << 20);
                g_stick = 0;
                __threadfence();
                atomicExch(&g_ready, 1u);
            }
        }
        __syncthreads();
    }

    // ---- Wait for guess (overlapped with in-flight loads) ----
    if (t == 0) {
        while (atomicAdd(&g_ready, 0u) == 0u) __nanosleep(64);
        s_cnt = 0;
    }
    __syncthreads();
    __threadfence();
    const float gf = g_gf;

    // ---- Filter + stage candidates ----
    #pragma unroll
    for (int i = 0; i < 8; i++) {
        int i4 = base4 + i * NT;
        float vv[4] = {v[i].x, v[i].y, v[i].z, v[i].w};
        #pragma unroll
        for (int c = 0; c < 4; c++) {
            if (vv[c] >= gf) {
                unsigned p = atomicAdd(&s_cnt, 1u);
                unsigned key = fkey(vv[c]);
                unsigned idx = ((unsigned)i4 << 2) + (unsigned)c;
                if (p < SCAP) { u.st.key[p] = key; u.st.idx[p] = idx; }
                else {
                    unsigned g = atomicAdd(&g_cand_cnt, 1u);
                    if (g < CANDCAP) { g_cand_key[g] = key; g_cand_idx[g] = idx; }
                }
            }
        }
    }
    __syncthreads();
    {
        unsigned nloc = min(s_cnt, SCAP);
        if (t == 0) s_gbase = atomicAdd(&g_cand_cnt, nloc);
        __syncthreads();
        for (unsigned i = t; i < nloc; i += NT) {
            unsigned g = s_gbase + i;
            if (g < CANDCAP) { g_cand_key[g] = u.st.key[i]; g_cand_idx[g] = u.st.idx[i]; }
        }
    }

    // ---- Finish ticket; last 148 become selectors ----
    __threadfence();
    __syncthreads();
    if (t == 0) s_tick = atomicAdd(&g_done, 1u);
    __syncthreads();
    unsigned tick = s_tick;
    if (tick < NCHUNKS - NB_SEL) return;
    const unsigned sel = tick - (NCHUNKS - NB_SEL);     // 0..147
    if (t == 0) {
        while (atomicAdd(&g_done, 0u) < NCHUNKS) __nanosleep(32);
    }
    __syncthreads();
    __threadfence();

    const unsigned base = g_base;
    const unsigned ncand = min(g_cand_cnt, CANDCAP);
    const unsigned cit = (ncand + NTHR_SEL - 1) / NTHR_SEL;
    const unsigned gid = sel * NT + t;

    // ---- Select pass 1: top-12-bit histogram of candidates ----
    for (int i = t; i < 4096; i += NT) u.hist[i] = 0;
    __syncthreads();
    for (unsigned s = 0; s < cit; s++) {
        unsigned j = gid + s * NTHR_SEL;
        bool vv = j < ncand;
        unsigned bin = vv ? (g_cand_key[j] >> 20) : 0u;
        wagg_add(u.hist, bin, vv);
    }
    __syncthreads();
    for (int i = t; i < 4096; i += NT) {
        unsigned c = u.hist[i];
        if (c) atomicAdd(&g_histA[i], c);
    }
    grid_bar(base + NB_SEL);                               // bar1
    suffix_pick<16>(g_histA, K_TOTAL, s_scan, &s_bin, &s_rem);
    const unsigned b12 = s_bin, rank1 = s_rem;

    // ---- Select pass 2: scatter top12>b12, compact ==b12, mid-12 hist ----
    for (int i = t; i < 4096; i += NT) u.hist[i] = 0;
    __syncthreads();
    for (unsigned s = 0; s < cit; s++) {
        unsigned j = gid + s * NTHR_SEL;
        bool vv = j < ncand;
        unsigned key = vv ? g_cand_key[j] : 0u;
        unsigned top = key >> 20;
        if (vv && top > b12)
            out[g_cand_idx[j]] = fmaxf(kval(key), 0.f);
        bool inbin = vv && (top == b12);
        unsigned slot = wagg_append(&g_side_cnt, inbin);
        if (inbin && slot < SIDECAP) {
            g_side_key[slot] = key;
            g_side_idx[slot] = g_cand_idx[j];
        }
        wagg_add(u.hist, (key >> 8) & 0xFFFu, inbin);
    }
    __syncthreads();
    for (int i = t; i < 4096; i += NT) {
        unsigned c = u.hist[i];
        if (c) atomicAdd(&g_histB[i], c);
    }
    grid_bar(base + 2 * NB_SEL);                           // bar2
    for (unsigned i = gid; i < 4096; i += NTHR_SEL) g_histA[i] = 0;  // safe: all reads pre-bar2
    suffix_pick<16>(g_histB, rank1, s_scan, &s_bin, &s_rem);
    const unsigned m12 = s_bin, rank2 = s_rem;

    const unsigned ns = min(g_side_cnt, SIDECAP);
    const unsigned sit = (ns + NTHR_SEL - 1) / NTHR_SEL;

    // ---- Side pass: scatter mid12>m12, low-8 hist ----
    if (t < 256) u.hist[t] = 0;
    __syncthreads();
    for (unsigned s = 0; s < sit; s++) {
        unsigned j = gid + s * NTHR_SEL;
        bool vv = j < ns;
        unsigned key = vv ? g_side_key[j] : 0u;
        unsigned mid = (key >> 8) & 0xFFFu;
        if (vv && mid > m12)
            out[g_side_idx[j]] = fmaxf(kval(key), 0.f);
        wagg_add(u.hist, key & 0xFFu, vv && (mid == m12));
    }
    __syncthreads();
    {
        unsigned c = u.hist[t];
        if (c) atomicAdd(&g_hist8[t], c);
    }
    grid_bar(base + 3 * NB_SEL);                           // bar3
    for (unsigned i = gid; i < 4096; i += NTHR_SEL) g_histB[i] = 0;  // safe: all reads pre-bar3
    suffix_pick<1>(g_hist8, rank2, s_scan, &s_bin, &s_rem);
    const unsigned lo8 = s_bin, need = s_rem;
    const unsigned count_eq = g_hist8[lo8];
    const bool ambig = (need != count_eq);
    const unsigned ck = (b12 << 20) | (m12 << 8) | lo8;
    const float rc = fmaxf(kval(ck), 0.f);

    // ---- Final side pass: last-bin winners, eq collection ----
    for (unsigned s = 0; s < sit; s++) {
        unsigned j = gid + s * NTHR_SEL;
        if (j < ns) {
            unsigned key = g_side_key[j];
            if ((key >> 8) == ((b12 << 12) | m12)) {
                unsigned lo = key & 0xFFu;
                if (lo > lo8) out[g_side_idx[j]] = fmaxf(kval(key), 0.f);
                else if (lo == lo8) {
                    if (!ambig) out[g_side_idx[j]] = rc;
                    else {
                        unsigned p = atomicAdd(&g_eq_cnt, 1u);
                        if (p < EQCAP) g_eq_idx[p] = g_side_idx[j];
                    }
                }
            }
        }
    }
    if (gid == 0) out[ntot] = (1.0f - EMA_E) * thr[0] + EMA_E * rc;
    grid_bar(base + 4 * NB_SEL);                           // bar4 (unconditional)

    // ---- Cleanup: all state last read before bar4 ----
    if (gid < 256) g_hist8[gid] = 0;
    if (gid == 0) {
        g_cand_cnt = 0;
        g_side_cnt = 0;
        g_done = 0;
        atomicExch(&g_ready, 0u);
    }
    if (sel == 0) {
        if (ambig) {
            // JAX tie-break: lowest flat index wins among equal-valued elems.
            unsigned ne = min(g_eq_cnt, EQCAP);
            __shared__ unsigned smin[256];
            __shared__ unsigned sbest;
            for (unsigned s2 = 0; s2 < need; s2++) {
                unsigned m = 0xFFFFFFFFu;
                for (unsigned j = t; j < ne; j += NT) m = min(m, g_eq_idx[j]);
                smin[t] = m;
                __syncthreads();
                for (int d = 128; d > 0; d >>= 1) {
                    if (t < d) smin[t] = min(smin[t], smin[t + d]);
                    __syncthreads();
                }
                if (t == 0) sbest = smin[0];
                __syncthreads();
                unsigned best = sbest;
                if (best == 0xFFFFFFFFu) break;
                for (unsigned j = t; j < ne; j += NT)
                    if (g_eq_idx[j] == best) g_eq_idx[j] = 0xFFFFFFFFu;
                if (t == 0) out[best] = rc;
                __syncthreads();
            }
        }
        if (t == 0) {
            g_eq_cnt = 0;
            g_base = base + 4 * NB_SEL;
        }
    }
}

// ---------------------------------------------------------------------------
extern "C" void kernel_launch(void* const* d_in, const int* in_sizes, int n_in,
                              void* d_out, int out_size) {
    const float* x   = (const float*)d_in[0];
    const float* thr = (const float*)d_in[1];
    float* out = (float*)d_out;

    int n = in_sizes[0];
    int n4 = n / 4;
    int ntot = out_size - 1;   // threshold in last output slot

    int nchunks = (n4 + CHUNK_F4 - 1) / CHUNK_F4;   // 3072 for this shape
    k_all<<<nchunks, NT>>>((const float4*)x, (float4*)out, n4, thr, out, ntot);
}